// round 13
// baseline (speedup 1.0000x reference)
#include <cuda_runtime.h>
#include <cuda_bf16.h>

typedef unsigned long long u64;

// Problem dims
#define T_DIM 512
#define B_DIM 32
#define I_DIM 512
#define H_DIM 512
#define G_DIM 2048                       // 4*H
#define BH    (B_DIM*H_DIM)
#define S_TBH (T_DIM*B_DIM*H_DIM)        // one [T,B,H] slab
#define NCTA 128

// Scratch: layer-0 pre-activations [T, B, 4H]
__device__ float g_pre[(size_t)T_DIM * B_DIM * G_DIM];

// Entry-barrier state (monotonic across graph replays; NEVER reset)
__device__ unsigned gSub[8 * 32];
__device__ unsigned gMaster;
__device__ unsigned gGen;
// Per-CTA dataflow counters (reset per launch behind entry barrier)
__device__ unsigned gStep[NCTA * 32];

// ---- f32x2 helpers ---------------------------------------------------------
__device__ __forceinline__ u64 ffma2(u64 a, u64 b, u64 c) {
    u64 d; asm("fma.rn.f32x2 %0,%1,%2,%3;" : "=l"(d) : "l"(a), "l"(b), "l"(c));
    return d;
}
__device__ __forceinline__ u64 fsplat(float a) {
    u64 r; asm("mov.b64 %0,{%1,%1};" : "=l"(r) : "f"(a)); return r;
}
__device__ __forceinline__ float2 funpack(u64 v) {
    float lo, hi; asm("mov.b64 {%0,%1},%2;" : "=f"(lo), "=f"(hi) : "l"(v));
    return make_float2(lo, hi);
}
// ---- release/acquire -------------------------------------------------------
__device__ __forceinline__ unsigned ld_acq(const unsigned* p) {
    unsigned v;
    asm volatile("ld.acquire.gpu.global.u32 %0,[%1];" : "=r"(v) : "l"(p));
    return v;
}
__device__ __forceinline__ void red_add_rel(unsigned* p, unsigned v) {
    asm volatile("red.release.gpu.global.add.u32 [%0],%1;" :: "l"(p), "r"(v));
}
__device__ __forceinline__ float sigf(float x) {
    return 1.f / (1.f + __expf(-x));
}

// ---------------------------------------------------------------------------
// GEMM for layer-0 input projection (proven, unchanged)
// ---------------------------------------------------------------------------
__global__ __launch_bounds__(256) void gemm_pre_kernel(
    const float* __restrict__ A,
    const float* __restrict__ W,
    const float* __restrict__ bih,
    const float* __restrict__ bhh,
    float* __restrict__ C)
{
    const int K = I_DIM;
    const int N = G_DIM;

    __shared__ float As[2][8][128];
    __shared__ float Bs[2][8][128];

    const int bm = blockIdx.y * 128;
    const int bn = blockIdx.x * 128;
    const int tid = threadIdx.x;
    const int tx = tid & 15;
    const int ty = tid >> 4;

    u64 acc2[8][4];
#pragma unroll
    for (int i = 0; i < 8; i++)
#pragma unroll
        for (int jp = 0; jp < 4; jp++) acc2[i][jp] = 0ull;

    const int lr = tid >> 1;
    const int lc = (tid & 1) * 4;
    const float* Aptr = A + (size_t)(bm + lr) * K + lc;
    const float* Wptr = W + (size_t)(bn + lr) * K + lc;

    float4 av = *(const float4*)(Aptr);
    float4 wv = *(const float4*)(Wptr);
    As[0][lc + 0][lr] = av.x; As[0][lc + 1][lr] = av.y;
    As[0][lc + 2][lr] = av.z; As[0][lc + 3][lr] = av.w;
    Bs[0][lc + 0][lr] = wv.x; Bs[0][lc + 1][lr] = wv.y;
    Bs[0][lc + 2][lr] = wv.z; Bs[0][lc + 3][lr] = wv.w;
    __syncthreads();

    for (int kt = 0; kt < 64; kt++) {
        const int cur = kt & 1;
        if (kt < 63) {
            av = *(const float4*)(Aptr + (kt + 1) * 8);
            wv = *(const float4*)(Wptr + (kt + 1) * 8);
        }
#pragma unroll
        for (int kk = 0; kk < 8; kk++) {
            float a[8];
            *(float4*)(a)     = *(const float4*)&As[cur][kk][ty * 8];
            *(float4*)(a + 4) = *(const float4*)&As[cur][kk][ty * 8 + 4];
            const ulonglong2* bp = (const ulonglong2*)&Bs[cur][kk][tx * 8];
            ulonglong2 q0 = bp[0], q1 = bp[1];
            u64 b2[4] = { q0.x, q0.y, q1.x, q1.y };
#pragma unroll
            for (int i = 0; i < 8; i++) {
                u64 a2 = fsplat(a[i]);
#pragma unroll
                for (int jp = 0; jp < 4; jp++)
                    acc2[i][jp] = ffma2(a2, b2[jp], acc2[i][jp]);
            }
        }
        if (kt < 63) {
            const int nxt = cur ^ 1;
            As[nxt][lc + 0][lr] = av.x; As[nxt][lc + 1][lr] = av.y;
            As[nxt][lc + 2][lr] = av.z; As[nxt][lc + 3][lr] = av.w;
            Bs[nxt][lc + 0][lr] = wv.x; Bs[nxt][lc + 1][lr] = wv.y;
            Bs[nxt][lc + 2][lr] = wv.z; Bs[nxt][lc + 3][lr] = wv.w;
        }
        __syncthreads();
    }

    float bias[8];
#pragma unroll
    for (int j = 0; j < 8; j++) {
        int col = bn + tx * 8 + j;
        bias[j] = bih[col] + bhh[col];
    }
#pragma unroll
    for (int i = 0; i < 8; i++) {
        int row = bm + ty * 8 + i;
        float* cp = C + (size_t)row * N + bn + tx * 8;
        float o[8];
#pragma unroll
        for (int jp = 0; jp < 4; jp++) {
            float2 v = funpack(acc2[i][jp]);
            o[2 * jp]     = v.x + bias[2 * jp];
            o[2 * jp + 1] = v.y + bias[2 * jp + 1];
        }
        *(float4*)(cp)     = make_float4(o[0], o[1], o[2], o[3]);
        *(float4*)(cp + 4) = make_float4(o[4], o[5], o[6], o[7]);
    }
}

// ---------------------------------------------------------------------------
// FUSED persistent 2-layer LSTM recurrence. 128 CTAs x 512 threads.
// CTA bx owns units j0..j0+3 of both layers (48 weight cols:
//   0..15 Whh0 | 16..31 Wih1 | 32..47 Whh1).
// Mainloop decomposition (traffic-minimal): warp = (kq in 0..7: 64-k slice,
// half in 0..1): phase B computes 16 cols of 0..31 over its slice for ALL
// 32 b; phase C computes 8 cols of 32..47. Partials sgB[8][32][32] and
// sgC[8][16][32] coexist -> single reduce after phase C.
// ---------------------------------------------------------------------------
__global__ __launch_bounds__(512, 1) void lstm_fused_kernel(
    const float* __restrict__ pre0,    // [T, B, 4H]
    const float* __restrict__ whh0,    // [4H, H]
    const float* __restrict__ wih1,    // [4H, I]
    const float* __restrict__ whh1,    // [4H, H]
    const float* __restrict__ bih1,    // [4H]
    const float* __restrict__ bhh1,    // [4H]
    float* __restrict__ out)           // [6, L, T, B, H]
{
    extern __shared__ float4 dsm4[];
    float4*     sW4  = dsm4;                        // 48*128 f4  = 24576 f
    float4*     tile4= dsm4 + 6144;                 // 4096 f4    = 16384 f
    float*      sgB  = (float*)(dsm4 + 10240);      // [8][32][32]=  8192 f
    float*      sgC  = sgB + 8192;                  // [8][16][32]=  4096 f
    float*      sAct = sgC + 4096;                  // [2][16*33] =  1056 f
    float*      sB1  = sAct + 1056;                 // 16 f
    float*      sc   = sB1 + 16;                    // [2][128]   =   256 f
    __shared__ unsigned base_s;

    const int tid = threadIdx.x;
    const int bx  = blockIdx.x;
    const int j0  = bx * 4;

    float* out_h0 = out;                                    // q=0, l=0
    float* out_h1 = out + (size_t)S_TBH;                    // q=0, l=1
    float* out_c0 = out + (size_t)2 * S_TBH;                // q=1, l=0
    float* out_c1 = out + (size_t)3 * S_TBH;                // q=1, l=1

    // ---- load 48 weight columns into smem
#pragma unroll
    for (int i = 0; i < 12; i++) {
        int f = tid + i * 512;              // float4 id 0..6143
        int col = f >> 7, k4 = f & 127;
        int cidx = (col < 16) ? col : ((col < 32) ? col - 16 : col - 32);
        const float* src = (col < 16) ? whh0 : ((col < 32) ? wih1 : whh1);
        int row = (cidx >> 2) * 512 + j0 + (cidx & 3);
        sW4[col * 128 + k4] = ((const float4*)src)[(size_t)row * 128 + k4];
    }
    if (tid < 16) {
        int row = (tid >> 2) * 512 + j0 + (tid & 3);
        sB1[tid] = bih1[row] + bhh1[row];
    }
    if (tid < 256) sc[tid] = 0.f;

    // ---- reset own counter; monotonic entry grid barrier
    if (tid == 0) {
        *(volatile unsigned*)&gStep[bx * 32] = 0u;
        base_s = *(volatile unsigned*)&gGen;
    }
    __syncthreads();
    if (tid == 0) {
        __threadfence();
        unsigned v = atomicAdd(&gSub[(bx & 7) * 32], 1u) + 1u;
        if ((v & 15u) == 0u) {
            unsigned m = atomicAdd(&gMaster, 1u) + 1u;
            if ((m & 7u) == 0u) atomicAdd(&gGen, 1u);
        }
        unsigned target = base_s + 1u;
        while ((int)(ld_acq(&gGen) - target) < 0) {}
        __threadfence();
    }
    __syncthreads();

    const int lane = tid & 31;
    const int b    = lane;
    const int w    = tid >> 5;
    const int kq   = w & 7;             // 64-k slice index (k4: kq*16..+16)
    const int half = w >> 3;            // col half (phase B) / col quarter (C)
    const int bsw  = b & 7;             // tile swizzle key
    // my producer counter: staged slice k4 = tid&127 -> produced by CTA tid&127
    const unsigned* myctr = &gStep[(tid & 127) * 32];
    // reduce role
    const int rc = tid >> 5;            // cidx 0..15
    const int rb = tid & 31;
    const float* prep = pre0 + (size_t)rb * G_DIM + (rc >> 2) * 512 + j0 + (rc & 3);
    // update role (tid<256)
    const int ul  = tid >> 7;           // layer
    const int ur  = tid & 127;
    const int ub  = ur >> 2;
    const int ujl = ur & 3;
    // gate-store role
    const int pb2 = tid >> 4;
    const int pc2 = tid & 15;

    const ulonglong2* t2 = (const ulonglong2*)tile4;

    for (int t = 0; t <= T_DIM; t++) {
        // pre0[t] scalar for reduce role (static data, before any wait)
        float pre_v = 0.f;
        if (t < T_DIM) pre_v = prep[(size_t)t * (B_DIM * G_DIM)];

        // ---- stage h0[t-1] with inline per-thread producer poll
        if (t > 0) {
            unsigned target = 8u * (unsigned)t;
            while (ld_acq(myctr) < target) {}
            const float4* hs0 = (const float4*)(out_h0 + (size_t)(t - 1) * BH);
#pragma unroll
            for (int i = 0; i < 8; i++) {
                int f = tid + i * 512;
                int bb = f >> 7, k4 = f & 127;
                tile4[bb * 128 + (k4 ^ (bb & 7))] = hs0[f];
            }
        } else {
#pragma unroll
            for (int i = 0; i < 8; i++) {
                int f = tid + i * 512;
                int bb = f >> 7, k4 = f & 127;
                tile4[bb * 128 + (k4 ^ (bb & 7))] = make_float4(0.f, 0.f, 0.f, 0.f);
            }
        }
        __syncthreads();

        // ---- phase B: cols half*16..+16 of [0..31] over 64-k slice, all b
        {
            u64 acc[16];
#pragma unroll
            for (int c = 0; c < 16; c++) acc[c] = 0ull;
            const int cbase = half * 16;
            const ulonglong2* wp = (const ulonglong2*)sW4 + cbase * 128 + kq * 16;
#pragma unroll 4
            for (int kk4 = 0; kk4 < 16; kk4++) {
                ulonglong2 hv = t2[b * 128 + ((kq * 16 + kk4) ^ bsw)];
#pragma unroll
                for (int c = 0; c < 16; c++) {
                    ulonglong2 wv = wp[c * 128 + kk4];
                    acc[c] = ffma2(hv.x, wv.x, acc[c]);
                    acc[c] = ffma2(hv.y, wv.y, acc[c]);
                }
            }
            float* sgw = sgB + kq * 1024 + b;
#pragma unroll
            for (int c = 0; c < 16; c++) {
                float2 v = funpack(acc[c]);
                sgw[(cbase + c) * 32] = v.x + v.y;
            }
        }
        __syncthreads();      // all warps done reading h0 tile

        // ---- restage tile with h1[t-2]
        if (t >= 2) {
            const float4* hs1 = (const float4*)(out_h1 + (size_t)(t - 2) * BH);
#pragma unroll
            for (int i = 0; i < 8; i++) {
                int f = tid + i * 512;
                int bb = f >> 7, k4 = f & 127;
                tile4[bb * 128 + (k4 ^ (bb & 7))] = hs1[f];
            }
        } else {
#pragma unroll
            for (int i = 0; i < 8; i++) {
                int f = tid + i * 512;
                int bb = f >> 7, k4 = f & 127;
                tile4[bb * 128 + (k4 ^ (bb & 7))] = make_float4(0.f, 0.f, 0.f, 0.f);
            }
        }
        __syncthreads();

        // ---- phase C: cols 32 + half*8..+8 over 64-k slice, all b
        {
            u64 acc[8];
#pragma unroll
            for (int c = 0; c < 8; c++) acc[c] = 0ull;
            const int cbase = 32 + half * 8;
            const ulonglong2* wp = (const ulonglong2*)sW4 + cbase * 128 + kq * 16;
#pragma unroll 4
            for (int kk4 = 0; kk4 < 16; kk4++) {
                ulonglong2 hv = t2[b * 128 + ((kq * 16 + kk4) ^ bsw)];
#pragma unroll
                for (int c = 0; c < 8; c++) {
                    ulonglong2 wv = wp[c * 128 + kk4];
                    acc[c] = ffma2(hv.x, wv.x, acc[c]);
                    acc[c] = ffma2(hv.y, wv.y, acc[c]);
                }
            }
            float* sgw = sgC + kq * 512 + b;
#pragma unroll
            for (int c = 0; c < 8; c++) {
                float2 v = funpack(acc[c]);
                sgw[(half * 8 + c) * 32] = v.x + v.y;
            }
        }
        __syncthreads();

        // ---- reduce + activations (512 threads: one cidx x one b, both layers)
        {
            float g0 = pre_v;
            float g1 = sB1[rc];
            const float* pB = sgB + rc * 32 + rb;
            const float* pC = sgC + rc * 32 + rb;
#pragma unroll
            for (int q = 0; q < 8; q++) {
                g0 += pB[q * 1024];
                g1 += pB[q * 1024 + 512] + pC[q * 512];
            }
            float a0, a1;
            if ((rc >> 2) == 2) { a0 = tanhf(g0); a1 = tanhf(g1); }
            else                { a0 = sigf(g0);  a1 = sigf(g1);  }
            sAct[rc * 33 + rb]       = a0;
            sAct[528 + rc * 33 + rb] = a1;
        }
        __syncthreads();

        // ---- pointwise update + release (8 warps)
        if (tid < 256) {
            const bool active = (ul == 0) ? (t < T_DIM) : (t >= 1);
            float cnew = 0.f;
            size_t idx = 0;
            if (active) {
                const float* sa = sAct + ul * 528;
                float it = sa[(0  + ujl) * 33 + ub];
                float ft = sa[(4  + ujl) * 33 + ub];
                float gt = sa[(8  + ujl) * 33 + ub];
                float ot = sa[(12 + ujl) * 33 + ub];
                float cold = sc[ul * 128 + ur];
                cnew = fmaf(ft, cold, it * gt);
                float hnew = ot * tanhf(cnew);
                sc[ul * 128 + ur] = cnew;
                int tt = (ul == 0) ? t : (t - 1);
                idx = (size_t)tt * BH + ub * H_DIM + j0 + ujl;
                (ul ? out_h1 : out_h0)[idx] = hnew;
            }
            __syncwarp();
            if ((tid & 31) == 0)
                red_add_rel(&gStep[bx * 32], 1u);     // own line, 8/step
            if (active)
                (ul ? out_c1 : out_c0)[idx] = cnew;   // off critical path
        }

        // ---- gate outputs i/f/g/o for both layers (after release)
        {
            int g = pc2 >> 2, jl = pc2 & 3;
            if (t < T_DIM) {
                float a = sAct[pc2 * 33 + pb2];
                float* dst = out + (size_t)(2 + g) * 2 * S_TBH
                             + (size_t)t * BH + pb2 * H_DIM + j0 + jl;
                *dst = a;
            }
            if (t >= 1) {
                float a = sAct[528 + pc2 * 33 + pb2];
                float* dst = out + (size_t)(2 + g) * 2 * S_TBH + S_TBH
                             + (size_t)(t - 1) * BH + pb2 * H_DIM + j0 + jl;
                *dst = a;
            }
        }
    }
}

// ---------------------------------------------------------------------------
extern "C" void kernel_launch(void* const* d_in, const int* in_sizes, int n_in,
                              void* d_out, int out_size)
{
    (void)in_sizes; (void)n_in; (void)out_size;
    const float* x    = (const float*)d_in[0];   // [T, B, I]
    const float* w_ih = (const float*)d_in[1];   // [L, 4H, I]
    const float* w_hh = (const float*)d_in[2];   // [L, 4H, H]
    const float* b_ih = (const float*)d_in[3];   // [L, 4H]
    const float* b_hh = (const float*)d_in[4];   // [L, 4H]
    float* out = (float*)d_out;                  // [6, L, T, B, H]

    float* pre;
    cudaGetSymbolAddress((void**)&pre, g_pre);

    const size_t fused_smem =
        (size_t)(24576 + 16384 + 8192 + 4096 + 1056 + 16 + 256) * sizeof(float);
    cudaFuncSetAttribute(lstm_fused_kernel,
                         cudaFuncAttributeMaxDynamicSharedMemorySize,
                         (int)fused_smem);

    dim3 ggrid(G_DIM / 128, (T_DIM * B_DIM) / 128);   // 16 x 128

    // Layer-0 input projection, then fused 2-layer recurrence
    gemm_pre_kernel<<<ggrid, 256>>>(x, w_ih, b_ih, b_hh, pre);
    lstm_fused_kernel<<<NCTA, 512, fused_smem>>>(
        pre,
        w_hh,                                   // Whh0
        w_ih + (size_t)G_DIM * I_DIM,           // Wih1
        w_hh + (size_t)G_DIM * H_DIM,           // Whh1
        b_ih + G_DIM,
        b_hh + G_DIM,
        out);
}

// round 15
// speedup vs baseline: 1.1874x; 1.1874x over previous
#include <cuda_runtime.h>
#include <cuda_bf16.h>

typedef unsigned long long u64;

// Problem dims
#define T_DIM 512
#define B_DIM 32
#define I_DIM 512
#define H_DIM 512
#define G_DIM 2048                       // 4*H
#define BH    (B_DIM*H_DIM)
#define S_TBH (T_DIM*B_DIM*H_DIM)        // one [T,B,H] slab
#define NREC  128                        // recurrence CTAs
#define NWRK  20                         // GEMM worker CTAs
#define NGRID (NREC + NWRK)

// Scratch: layer-0 pre-activations [T, B, 4H]
__device__ float g_pre[(size_t)T_DIM * B_DIM * G_DIM];

// Entry-barrier state (monotonic across graph replays; NEVER reset)
__device__ unsigned gSub[8 * 32];
__device__ unsigned gMaster;
__device__ unsigned gGen;
// Per-CTA dataflow counters (reset per launch behind entry barrier)
__device__ unsigned gStep[NREC * 32];
// GEMM progress counters, MONOTONIC (16 per chunk per launch), padded lines
__device__ unsigned gPreCnt[128 * 32];
// Launch epoch (incremented once per launch, at the very end, by CTA 0)
__device__ unsigned gLaunch;

// ---- f32x2 helpers ---------------------------------------------------------
__device__ __forceinline__ u64 ffma2(u64 a, u64 b, u64 c) {
    u64 d; asm("fma.rn.f32x2 %0,%1,%2,%3;" : "=l"(d) : "l"(a), "l"(b), "l"(c));
    return d;
}
__device__ __forceinline__ u64 fsplat(float a) {
    u64 r; asm("mov.b64 %0,{%1,%1};" : "=l"(r) : "f"(a)); return r;
}
__device__ __forceinline__ float2 funpack(u64 v) {
    float lo, hi; asm("mov.b64 {%0,%1},%2;" : "=f"(lo), "=f"(hi) : "l"(v));
    return make_float2(lo, hi);
}
// ---- release/acquire -------------------------------------------------------
__device__ __forceinline__ unsigned ld_acq(const unsigned* p) {
    unsigned v;
    asm volatile("ld.acquire.gpu.global.u32 %0,[%1];" : "=r"(v) : "l"(p));
    return v;
}
__device__ __forceinline__ void red_add_rel(unsigned* p, unsigned v) {
    asm volatile("red.release.gpu.global.add.u32 [%0],%1;" :: "l"(p), "r"(v));
}
__device__ __forceinline__ float sigf(float x) {
    return 1.f / (1.f + __expf(-x));
}

// ---------------------------------------------------------------------------
// MEGA persistent kernel, grid = 148 x 512.
//   CTAs 0..127  : fused 2-layer LSTM recurrence (R9-proven body)
//   CTAs 128..147: GEMM workers for the layer-0 input projection, t-major,
//                  two 128x128 tiles per CTA iteration (one per 256-thr half)
// ---------------------------------------------------------------------------
__global__ __launch_bounds__(512, 1) void lstm_mega_kernel(
    const float* __restrict__ x,       // [T, B, I]
    const float* __restrict__ w_ih,    // [L, 4H, I]
    const float* __restrict__ w_hh,    // [L, 4H, H]
    const float* __restrict__ b_ih,    // [L, 4H]
    const float* __restrict__ b_hh,    // [L, 4H]
    float* __restrict__ pre0,          // scratch [T, B, 4H]
    float* __restrict__ out)           // [6, L, T, B, H]
{
    extern __shared__ float smf[];
    const int tid = threadIdx.x;
    const int bx  = blockIdx.x;

    const float* whh0 = w_hh;
    const float* wih1 = w_ih + (size_t)G_DIM * I_DIM;
    const float* whh1 = w_hh + (size_t)G_DIM * H_DIM;

    // =======================================================================
    // GEMM WORKER PATH (CTAs 128..147)
    // =======================================================================
    if (bx >= NREC) {
        const int half = tid >> 8;            // 0 or 1
        const int htid = tid & 255;
        float* sm = smf + half * 4096;        // As[2][8][128] | Bs[2][8][128]
        float* As = sm;
        float* Bs = sm + 2048;
        const int widx = bx - NREC;           // 0..19
        const int tx = htid & 15;
        const int ty = htid >> 4;
        const int lr = htid >> 1;
        const int lc = (htid & 1) * 4;

        for (int it = 0; it < 52; it++) {
            int tile0 = it * (NWRK * 2) + widx * 2;
            if (tile0 >= 2048) break;         // uniform per CTA (both halves)
            int tile = tile0 + half;
            int tc = tile >> 4;               // t-chunk (4 timesteps)
            int nt = tile & 15;
            int bm = tc * 128;
            int bn = nt * 128;

            u64 acc2[8][4];
#pragma unroll
            for (int i = 0; i < 8; i++)
#pragma unroll
                for (int jp = 0; jp < 4; jp++) acc2[i][jp] = 0ull;

            const float* Aptr = x    + (size_t)(bm + lr) * I_DIM + lc;
            const float* Wptr = w_ih + (size_t)(bn + lr) * I_DIM + lc;

            float4 av = *(const float4*)(Aptr);
            float4 wv = *(const float4*)(Wptr);
            As[(lc + 0) * 128 + lr] = av.x; As[(lc + 1) * 128 + lr] = av.y;
            As[(lc + 2) * 128 + lr] = av.z; As[(lc + 3) * 128 + lr] = av.w;
            Bs[(lc + 0) * 128 + lr] = wv.x; Bs[(lc + 1) * 128 + lr] = wv.y;
            Bs[(lc + 2) * 128 + lr] = wv.z; Bs[(lc + 3) * 128 + lr] = wv.w;
            __syncthreads();

            for (int kt = 0; kt < 64; kt++) {
                const int cur = (kt & 1) * 1024;
                if (kt < 63) {
                    av = *(const float4*)(Aptr + (kt + 1) * 8);
                    wv = *(const float4*)(Wptr + (kt + 1) * 8);
                }
#pragma unroll
                for (int kk = 0; kk < 8; kk++) {
                    float a[8];
                    *(float4*)(a)     = *(const float4*)&As[cur + kk * 128 + ty * 8];
                    *(float4*)(a + 4) = *(const float4*)&As[cur + kk * 128 + ty * 8 + 4];
                    const ulonglong2* bp = (const ulonglong2*)&Bs[cur + kk * 128 + tx * 8];
                    ulonglong2 q0 = bp[0], q1 = bp[1];
                    u64 b2[4] = { q0.x, q0.y, q1.x, q1.y };
#pragma unroll
                    for (int i = 0; i < 8; i++) {
                        u64 a2 = fsplat(a[i]);
#pragma unroll
                        for (int jp = 0; jp < 4; jp++)
                            acc2[i][jp] = ffma2(a2, b2[jp], acc2[i][jp]);
                    }
                }
                if (kt < 63) {
                    const int nxt = ((kt & 1) ^ 1) * 1024;
                    As[nxt + (lc + 0) * 128 + lr] = av.x;
                    As[nxt + (lc + 1) * 128 + lr] = av.y;
                    As[nxt + (lc + 2) * 128 + lr] = av.z;
                    As[nxt + (lc + 3) * 128 + lr] = av.w;
                    Bs[nxt + (lc + 0) * 128 + lr] = wv.x;
                    Bs[nxt + (lc + 1) * 128 + lr] = wv.y;
                    Bs[nxt + (lc + 2) * 128 + lr] = wv.z;
                    Bs[nxt + (lc + 3) * 128 + lr] = wv.w;
                }
                __syncthreads();
            }

            float bias[8];
#pragma unroll
            for (int j = 0; j < 8; j++) {
                int col = bn + tx * 8 + j;
                bias[j] = b_ih[col] + b_hh[col];
            }
#pragma unroll
            for (int i = 0; i < 8; i++) {
                int row = bm + ty * 8 + i;
                float* cp = pre0 + (size_t)row * G_DIM + bn + tx * 8;
                float o[8];
#pragma unroll
                for (int jp = 0; jp < 4; jp++) {
                    float2 v = funpack(acc2[i][jp]);
                    o[2 * jp]     = v.x + bias[2 * jp];
                    o[2 * jp + 1] = v.y + bias[2 * jp + 1];
                }
                *(float4*)(cp)     = make_float4(o[0], o[1], o[2], o[3]);
                *(float4*)(cp + 4) = make_float4(o[4], o[5], o[6], o[7]);
            }
            __syncthreads();                  // all stores of both halves done
            if (htid == 0)
                red_add_rel(&gPreCnt[tc * 32], 1u);
        }
        return;
    }

    // =======================================================================
    // RECURRENCE PATH (CTAs 0..127) — R9-proven body + gPreCnt poll
    // =======================================================================
    float*  sW   = smf;                         // 48*512      = 24576 f
    float4* tile4= (float4*)(smf + 24576);      // 4096 float4 = 16384 f
    float*  sg   = smf + 24576 + 16384;         // [4][48][32] = 6144 f
    float*  sAct = sg + 6144;                   // [2][16*33]  = 1056 f
    float*  sB1  = sAct + 1056;                 // 16 f
    float*  sc   = sB1 + 16;                    // [2][128]    = 256 f
    float4* sW4  = (float4*)sW;
    __shared__ unsigned base_s;
    __shared__ unsigned lbase_s;

    const int j0  = bx * 4;

    float* out_h0 = out;                                    // q=0, l=0
    float* out_h1 = out + (size_t)S_TBH;                    // q=0, l=1
    float* out_c0 = out + (size_t)2 * S_TBH;                // q=1, l=0
    float* out_c1 = out + (size_t)3 * S_TBH;                // q=1, l=1

    // ---- load 48 weight columns into smem
#pragma unroll
    for (int i = 0; i < 12; i++) {
        int f = tid + i * 512;              // float4 id 0..6143
        int col = f >> 7, k4 = f & 127;
        int cidx = (col < 16) ? col : ((col < 32) ? col - 16 : col - 32);
        const float* src = (col < 16) ? whh0 : ((col < 32) ? wih1 : whh1);
        int row = (cidx >> 2) * 512 + j0 + (cidx & 3);
        sW4[col * 128 + k4] = ((const float4*)src)[(size_t)row * 128 + k4];
    }
    if (tid < 16) {
        int row = (tid >> 2) * 512 + j0 + (tid & 3);
        sB1[tid] = b_ih[G_DIM + row] + b_hh[G_DIM + row];
    }
    if (tid < 256) sc[tid] = 0.f;

    // ---- reset own counter; capture epochs; monotonic entry grid barrier
    if (tid == 0) {
        *(volatile unsigned*)&gStep[bx * 32] = 0u;
        base_s  = *(volatile unsigned*)&gGen;
        lbase_s = *(volatile unsigned*)&gLaunch;
    }
    __syncthreads();
    if (tid == 0) {
        __threadfence();
        unsigned v = atomicAdd(&gSub[(bx & 7) * 32], 1u) + 1u;
        if ((v & 15u) == 0u) {
            unsigned m = atomicAdd(&gMaster, 1u) + 1u;
            if ((m & 7u) == 0u) atomicAdd(&gGen, 1u);
        }
        unsigned target = base_s + 1u;
        while ((int)(ld_acq(&gGen) - target) < 0) {}
        __threadfence();
    }
    __syncthreads();
    const unsigned pre_target = 16u * (lbase_s + 1u);

    const int lane = tid & 31;
    const int b    = lane;
    const int w    = tid >> 5;
    const int kq   = w & 3;             // 128-k slice
    const int qt   = w >> 2;            // col quarter
    const int bsw  = b & 7;             // tile swizzle key
    // reduce role
    const int rc = tid >> 5;            // cidx 0..15
    const int rb = tid & 31;
    const float* prep = pre0 + (size_t)rb * G_DIM + (rc >> 2) * 512 + j0 + (rc & 3);
    // update role (tid<256)
    const int ul  = tid >> 7;           // layer
    const int ur  = tid & 127;
    const int ub  = ur >> 2;
    const int ujl = ur & 3;
    // gate-store role
    const int pb2 = tid >> 4;
    const int pc2 = tid & 15;

    const ulonglong2* t2 = (const ulonglong2*)tile4;

    for (int t = 0; t <= T_DIM; t++) {
        // ---- poll barrier: h producers (t>0) + pre chunk (t<T)
        if (tid < 128 && t > 0) {
            unsigned target = 8u * (unsigned)t;
            while (ld_acq(&gStep[tid * 32]) < target) {}
        }
        if (tid == 128 && t < T_DIM) {
            while (ld_acq(&gPreCnt[(t >> 2) * 32]) < pre_target) {}
        }
        __syncthreads();

        // pre0[t] scalar (chunk guaranteed ready by poll barrier)
        float pre_v = 0.f;
        if (t < T_DIM) pre_v = prep[(size_t)t * (B_DIM * G_DIM)];

        // prefetch h1[t-2] into registers (zeros when t<2)
        float4 hr[8];
        if (t >= 2) {
            const float4* hs1 = (const float4*)(out_h1 + (size_t)(t - 2) * BH);
#pragma unroll
            for (int i = 0; i < 8; i++) hr[i] = hs1[tid + i * 512];
        } else {
#pragma unroll
            for (int i = 0; i < 8; i++) hr[i] = make_float4(0.f, 0.f, 0.f, 0.f);
        }

        // stage h0[t-1] (zeros at t==0)
        if (t > 0) {
            const float4* hs0 = (const float4*)(out_h0 + (size_t)(t - 1) * BH);
#pragma unroll
            for (int i = 0; i < 8; i++) {
                int f = tid + i * 512;
                int bb = f >> 7, k4 = f & 127;
                tile4[bb * 128 + (k4 ^ (bb & 7))] = hs0[f];
            }
        } else {
#pragma unroll
            for (int i = 0; i < 8; i++) {
                int f = tid + i * 512;
                int bb = f >> 7, k4 = f & 127;
                tile4[bb * 128 + (k4 ^ (bb & 7))] = make_float4(0.f, 0.f, 0.f, 0.f);
            }
        }
        __syncthreads();

        // ---- phase B: cols 0..31 (recur0 + pre1) from h0 tile
        {
            u64 acc[8];
#pragma unroll
            for (int c = 0; c < 8; c++) acc[c] = 0ull;
            const int cbase = qt * 8;
            const ulonglong2* wp = (const ulonglong2*)(sW + cbase * 512) + kq * 32;
#pragma unroll 4
            for (int kk4 = 0; kk4 < 32; kk4++) {
                ulonglong2 hv = t2[b * 128 + ((kq * 32 + kk4) ^ bsw)];
#pragma unroll
                for (int c = 0; c < 8; c++) {
                    ulonglong2 wv = wp[c * 128 + kk4];
                    acc[c] = ffma2(hv.x, wv.x, acc[c]);
                    acc[c] = ffma2(hv.y, wv.y, acc[c]);
                }
            }
            float* sgw = sg + kq * 1536 + b;
#pragma unroll
            for (int c = 0; c < 8; c++) {
                float2 v = funpack(acc[c]);
                sgw[(cbase + c) * 32] = v.x + v.y;
            }
        }
        __syncthreads();      // all warps done reading h0 tile

        // ---- restage tile with h1[t-2] from registers
#pragma unroll
        for (int i = 0; i < 8; i++) {
            int f = tid + i * 512;
            int bb = f >> 7, k4 = f & 127;
            tile4[bb * 128 + (k4 ^ (bb & 7))] = hr[i];
        }
        __syncthreads();

        // ---- phase C: cols 32..47 (recur1) from h1 tile
        {
            u64 acc[4];
#pragma unroll
            for (int c = 0; c < 4; c++) acc[c] = 0ull;
            const int cbase = 32 + qt * 4;
            const ulonglong2* wp = (const ulonglong2*)(sW + cbase * 512) + kq * 32;
#pragma unroll 4
            for (int kk4 = 0; kk4 < 32; kk4++) {
                ulonglong2 hv = t2[b * 128 + ((kq * 32 + kk4) ^ bsw)];
#pragma unroll
                for (int c = 0; c < 4; c++) {
                    ulonglong2 wv = wp[c * 128 + kk4];
                    acc[c] = ffma2(hv.x, wv.x, acc[c]);
                    acc[c] = ffma2(hv.y, wv.y, acc[c]);
                }
            }
            float* sgw = sg + kq * 1536 + b;
#pragma unroll
            for (int c = 0; c < 4; c++) {
                float2 v = funpack(acc[c]);
                sgw[(cbase + c) * 32] = v.x + v.y;
            }
        }
        __syncthreads();

        // ---- reduce + activations (512 threads: one cidx x one b, both layers)
        {
            const float* sgr = sg + rb;
            float g0 = pre_v;
            float g1 = sB1[rc];
#pragma unroll
            for (int q = 0; q < 4; q++) {
                const float* p = sgr + q * 1536;
                g0 += p[rc * 32];
                g1 += p[(16 + rc) * 32] + p[(32 + rc) * 32];
            }
            float a0, a1;
            if ((rc >> 2) == 2) { a0 = tanhf(g0); a1 = tanhf(g1); }
            else                { a0 = sigf(g0);  a1 = sigf(g1);  }
            sAct[rc * 33 + rb]       = a0;
            sAct[528 + rc * 33 + rb] = a1;
        }
        __syncthreads();

        // ---- pointwise update + release (8 warps)
        if (tid < 256) {
            const bool active = (ul == 0) ? (t < T_DIM) : (t >= 1);
            float cnew = 0.f;
            size_t idx = 0;
            if (active) {
                const float* sa = sAct + ul * 528;
                float it = sa[(0  + ujl) * 33 + ub];
                float ft = sa[(4  + ujl) * 33 + ub];
                float gt = sa[(8  + ujl) * 33 + ub];
                float ot = sa[(12 + ujl) * 33 + ub];
                float cold = sc[ul * 128 + ur];
                cnew = fmaf(ft, cold, it * gt);
                float hnew = ot * tanhf(cnew);
                sc[ul * 128 + ur] = cnew;
                int tt = (ul == 0) ? t : (t - 1);
                idx = (size_t)tt * BH + ub * H_DIM + j0 + ujl;
                (ul ? out_h1 : out_h0)[idx] = hnew;
            }
            __syncwarp();
            if ((tid & 31) == 0)
                red_add_rel(&gStep[bx * 32], 1u);     // own line, 8/step
            if (active)
                (ul ? out_c1 : out_c0)[idx] = cnew;   // off critical path
        }

        // ---- gate outputs i/f/g/o for both layers (after release)
        {
            int g = pc2 >> 2, jl = pc2 & 3;
            if (t < T_DIM) {
                float a = sAct[pc2 * 33 + pb2];
                float* dst = out + (size_t)(2 + g) * 2 * S_TBH
                             + (size_t)t * BH + pb2 * H_DIM + j0 + jl;
                *dst = a;
            }
            if (t >= 1) {
                float a = sAct[528 + pc2 * 33 + pb2];
                float* dst = out + (size_t)(2 + g) * 2 * S_TBH + S_TBH
                             + (size_t)(t - 1) * BH + pb2 * H_DIM + j0 + jl;
                *dst = a;
            }
        }
    }

    // ---- advance launch epoch (CTA 0 finishes only after all chunks were
    // consumed and all CTAs' reads of gLaunch happened at entry)
    if (bx == 0 && tid == 0) red_add_rel(&gLaunch, 1u);
}

// ---------------------------------------------------------------------------
extern "C" void kernel_launch(void* const* d_in, const int* in_sizes, int n_in,
                              void* d_out, int out_size)
{
    (void)in_sizes; (void)n_in; (void)out_size;
    const float* x    = (const float*)d_in[0];   // [T, B, I]
    const float* w_ih = (const float*)d_in[1];   // [L, 4H, I]
    const float* w_hh = (const float*)d_in[2];   // [L, 4H, H]
    const float* b_ih = (const float*)d_in[3];   // [L, 4H]
    const float* b_hh = (const float*)d_in[4];   // [L, 4H]
    float* out = (float*)d_out;                  // [6, L, T, B, H]

    float* pre;
    cudaGetSymbolAddress((void**)&pre, g_pre);

    const size_t mega_smem =
        (size_t)(24576 + 16384 + 6144 + 1056 + 16 + 256) * sizeof(float);
    cudaFuncSetAttribute(lstm_mega_kernel,
                         cudaFuncAttributeMaxDynamicSharedMemorySize,
                         (int)mega_smem);

    lstm_mega_kernel<<<NGRID, 512, mega_smem>>>(
        x, w_ih, w_hh, b_ih, b_hh, pre, out);
}